// round 1
// baseline (speedup 1.0000x reference)
#include <cuda_runtime.h>

// Input:  x [6144 x 6144] fp32, weight [3 x 3] fp32
// Output: out [2048*2048] fp32,  out[w*2048+h] = -dot(weight, x[3w:3w+3, 3h:3h+3]) / 0.924458
//
// Pure HBM-streaming: each input byte read exactly once. One thread computes
// 4 adjacent outputs (12 contiguous input floats per row = 3 aligned float4
// loads x 3 rows), writes one float4.

#define XW 6144
#define NH 2048          // output cols (and rows)
#define GROUPS_PER_ROW 512  // NH / 4

__global__ __launch_bounds__(256) void conv3x3_stride3_kernel(
    const float* __restrict__ x,
    const float* __restrict__ wgt,
    float* __restrict__ out)
{
    int idx = blockIdx.x * blockDim.x + threadIdx.x;   // 0 .. 2048*512-1
    // row of output = idx / 512, horizontal group = idx % 512
    int w = idx >> 9;
    int g = idx & (GROUPS_PER_ROW - 1);
    if (w >= NH) return;

    // weight: 9 uniform broadcast loads (L1/L2 hit after first warp)
    float k0 = wgt[0], k1 = wgt[1], k2 = wgt[2];
    float k3 = wgt[3], k4 = wgt[4], k5 = wgt[5];
    float k6 = wgt[6], k7 = wgt[7], k8 = wgt[8];

    const float scale = (float)(-1.0 / 0.924458);

    // base input pointer: rows 3w..3w+2, starting column 12*g (48g bytes, 16B aligned)
    const float* base = x + (size_t)(3 * w) * XW + 12 * g;

    float4 a0 = *(const float4*)(base);
    float4 a1 = *(const float4*)(base + 4);
    float4 a2 = *(const float4*)(base + 8);
    float4 b0 = *(const float4*)(base + XW);
    float4 b1 = *(const float4*)(base + XW + 4);
    float4 b2 = *(const float4*)(base + XW + 8);
    float4 c0 = *(const float4*)(base + 2 * XW);
    float4 c1 = *(const float4*)(base + 2 * XW + 4);
    float4 c2 = *(const float4*)(base + 2 * XW + 8);

    float r0[12] = {a0.x, a0.y, a0.z, a0.w, a1.x, a1.y, a1.z, a1.w, a2.x, a2.y, a2.z, a2.w};
    float r1[12] = {b0.x, b0.y, b0.z, b0.w, b1.x, b1.y, b1.z, b1.w, b2.x, b2.y, b2.z, b2.w};
    float r2[12] = {c0.x, c0.y, c0.z, c0.w, c1.x, c1.y, c1.z, c1.w, c2.x, c2.y, c2.z, c2.w};

    float4 res;
    float* rp = (float*)&res;
#pragma unroll
    for (int j = 0; j < 4; j++) {
        float s = k0 * r0[3 * j] + k1 * r0[3 * j + 1] + k2 * r0[3 * j + 2]
                + k3 * r1[3 * j] + k4 * r1[3 * j + 1] + k5 * r1[3 * j + 2]
                + k6 * r2[3 * j] + k7 * r2[3 * j + 1] + k8 * r2[3 * j + 2];
        rp[j] = s * scale;
    }

    // output index: w*2048 + 4g floats = float4 index (w*512 + g) = idx
    ((float4*)out)[idx] = res;
}

extern "C" void kernel_launch(void* const* d_in, const int* in_sizes, int n_in,
                              void* d_out, int out_size)
{
    const float* x   = (const float*)d_in[0];
    const float* wgt = (const float*)d_in[1];
    float* out = (float*)d_out;

    int total_threads = NH * GROUPS_PER_ROW;   // 1,048,576
    int block = 256;
    int grid = (total_threads + block - 1) / block;  // 4096
    conv3x3_stride3_kernel<<<grid, block>>>(x, wgt, out);
}